// round 1
// baseline (speedup 1.0000x reference)
#include <cuda_runtime.h>
#include <cstdint>

#define NN      50000
#define E_RSR   3000000
#define E_RTR   1000000
#define E_RUR   200000
#define E_TOT   (E_RSR + E_RTR + E_RUR)

// ---------------- device scratch (no dynamic allocation allowed) ----------------
__device__ float g_rinv_out[3 * NN];   // per-relation rsqrt(out-degree)  (also deg counter)
__device__ float g_rinv_in [3 * NN];   // per-relation rsqrt(in-degree)   (also deg counter)
__device__ float g_hr[3][NN * 16];     // per-relation pre-aggregation features
__device__ float g_acc1[NN * 16];      // layer-1 shared accumulator (rinv_in folded in)
__device__ float g_gv[3 * NN];         // layer-2 per-relation scalar features
__device__ int   g_src32[E_TOT];
__device__ int   g_dst32[E_TOT];
__device__ int   g_is64;

// ---------------- dtype probe: int64 indices have zero high words ----------------
__global__ void k_probe(const unsigned* p) {
    if (threadIdx.x == 0) {
        int all0 = 1;
        #pragma unroll 1
        for (int k = 0; k < 64; k++)
            if (p[2 * k + 1] != 0u) { all0 = 0; break; }
        g_is64 = all0;
    }
}

// ---------------- zero scratch + init output with summed layer-2 bias ----------------
__global__ void k_init(float* out, const float* __restrict__ b2) {
    int i = blockIdx.x * blockDim.x + threadIdx.x;
    int stride = gridDim.x * blockDim.x;
    for (int j = i; j < NN * 16; j += stride) g_acc1[j] = 0.f;
    for (int j = i; j < 3 * NN; j += stride) { g_rinv_out[j] = 0.f; g_rinv_in[j] = 0.f; }
    float b2s = b2[0] + b2[1] + b2[2];
    for (int j = i; j < NN; j += stride) out[j] = b2s;
}

// ---------------- convert indices to int32 + count degrees ----------------
__global__ void k_convert(const void* s0, const void* d0,
                          const void* s1, const void* d1,
                          const void* s2, const void* d2) {
    int i = blockIdx.x * blockDim.x + threadIdx.x;
    if (i >= E_TOT) return;
    int r, e, off;
    const void *sp, *dp;
    if (i < E_RSR)                { r = 0; e = i;                 off = 0;             sp = s0; dp = d0; }
    else if (i < E_RSR + E_RTR)   { r = 1; e = i - E_RSR;         off = E_RSR;         sp = s1; dp = d1; }
    else                          { r = 2; e = i - E_RSR - E_RTR; off = E_RSR + E_RTR; sp = s2; dp = d2; }
    int s, d;
    if (g_is64) {
        s = (int)((const long long*)sp)[e];
        d = (int)((const long long*)dp)[e];
    } else {
        s = ((const int*)sp)[e];
        d = ((const int*)dp)[e];
    }
    g_src32[off + e] = s;
    g_dst32[off + e] = d;
    atomicAdd(&g_rinv_out[r * NN + s], 1.f);
    atomicAdd(&g_rinv_in [r * NN + d], 1.f);
}

// ---------------- deg -> rsqrt(max(deg,1)) ----------------
__global__ void k_findeg() {
    int i = blockIdx.x * blockDim.x + threadIdx.x;
    if (i >= 3 * NN) return;
    g_rinv_out[i] = rsqrtf(fmaxf(g_rinv_out[i], 1.f));
    g_rinv_in[i]  = rsqrtf(fmaxf(g_rinv_in[i],  1.f));
}

// ---------------- layer-1 transform: hr[r][n] = (x[n]*rinv_out[r][n]) @ W1[r] ----------------
__global__ void k_transform1(const float* __restrict__ x, const float* __restrict__ W1) {
    __shared__ float sW[3 * 32 * 16];
    for (int j = threadIdx.x; j < 1536; j += blockDim.x) sW[j] = W1[j];
    __syncthreads();
    int n = blockIdx.x * blockDim.x + threadIdx.x;
    if (n >= NN) return;
    float xv[32];
    const float4* xp = (const float4*)(x + (size_t)n * 32);
    #pragma unroll
    for (int q = 0; q < 8; q++) {
        float4 v = xp[q];
        xv[4 * q + 0] = v.x; xv[4 * q + 1] = v.y; xv[4 * q + 2] = v.z; xv[4 * q + 3] = v.w;
    }
    #pragma unroll
    for (int r = 0; r < 3; r++) {
        float rv = g_rinv_out[r * NN + n];
        float o[16];
        #pragma unroll
        for (int j = 0; j < 16; j++) o[j] = 0.f;
        #pragma unroll
        for (int k = 0; k < 32; k++) {
            float xk = xv[k];
            const float* w = &sW[r * 512 + k * 16];
            #pragma unroll
            for (int j = 0; j < 16; j++) o[j] = fmaf(xk, w[j], o[j]);
        }
        float4* hp = (float4*)&g_hr[r][n * 16];
        #pragma unroll
        for (int q = 0; q < 4; q++) {
            float4 v;
            v.x = o[4 * q + 0] * rv; v.y = o[4 * q + 1] * rv;
            v.z = o[4 * q + 2] * rv; v.w = o[4 * q + 3] * rv;
            hp[q] = v;
        }
    }
}

// ---------------- layer-1 SpMM: acc1[dst] += hr[r][src] * rinv_in[r][dst] ----------------
__device__ __forceinline__ void red_add_v4(float* p, float a, float b, float c, float d) {
    asm volatile("red.global.add.v4.f32 [%0], {%1, %2, %3, %4};"
                 :: "l"(p), "f"(a), "f"(b), "f"(c), "f"(d) : "memory");
}

__global__ void k_spmm1(int r, int off, int E) {
    long long t = (long long)blockIdx.x * blockDim.x + threadIdx.x;
    int e = (int)(t >> 2);
    int q = (int)(t & 3);
    if (e >= E) return;
    int s = g_src32[off + e];
    int d = g_dst32[off + e];
    float w = __ldg(&g_rinv_in[r * NN + d]);
    float4 v = *(const float4*)&g_hr[r][s * 16 + q * 4];
    red_add_v4(&g_acc1[d * 16 + q * 4], v.x * w, v.y * w, v.z * w, v.w * w);
}

// ---------------- relu + bias, then layer-2 projection (16 -> 1, per relation) ----------------
__global__ void k_relu_g(const float* __restrict__ b1, const float* __restrict__ W2) {
    int n = blockIdx.x * blockDim.x + threadIdx.x;
    if (n >= NN) return;
    float h[16];
    const float4* ap = (const float4*)&g_acc1[n * 16];
    #pragma unroll
    for (int q = 0; q < 4; q++) {
        float4 v = ap[q];
        h[4 * q + 0] = v.x; h[4 * q + 1] = v.y; h[4 * q + 2] = v.z; h[4 * q + 3] = v.w;
    }
    #pragma unroll
    for (int k = 0; k < 16; k++) {
        float bsum = __ldg(&b1[k]) + __ldg(&b1[16 + k]) + __ldg(&b1[32 + k]);
        h[k] = fmaxf(h[k] + bsum, 0.f);
    }
    #pragma unroll
    for (int r = 0; r < 3; r++) {
        float acc = 0.f;
        #pragma unroll
        for (int k = 0; k < 16; k++) acc = fmaf(h[k], __ldg(&W2[r * 16 + k]), acc);
        g_gv[r * NN + n] = acc * g_rinv_out[r * NN + n];
    }
}

// ---------------- layer-2 scalar SpMM: out[dst] += gv[r][src] * rinv_in[r][dst] ----------------
__global__ void k_spmm2(int r, int off, int E, float* out) {
    int e = blockIdx.x * blockDim.x + threadIdx.x;
    if (e >= E) return;
    int s = g_src32[off + e];
    int d = g_dst32[off + e];
    atomicAdd(&out[d], g_gv[r * NN + s] * __ldg(&g_rinv_in[r * NN + d]));
}

// =====================================================================================
extern "C" void kernel_launch(void* const* d_in, const int* in_sizes, int n_in,
                              void* d_out, int out_size) {
    const float* x  = (const float*)d_in[0];
    const void*  s0 = d_in[1]; const void* d0 = d_in[2];
    const void*  s1 = d_in[3]; const void* d1 = d_in[4];
    const void*  s2 = d_in[5]; const void* d2 = d_in[6];
    const float* W1 = (const float*)d_in[7];
    const float* b1 = (const float*)d_in[8];
    const float* W2 = (const float*)d_in[9];
    const float* b2 = (const float*)d_in[10];
    float* out = (float*)d_out;

    k_probe<<<1, 32>>>((const unsigned*)s0);
    k_init<<<1024, 256>>>(out, b2);
    k_convert<<<(E_TOT + 255) / 256, 256>>>(s0, d0, s1, d1, s2, d2);
    k_findeg<<<(3 * NN + 255) / 256, 256>>>();
    k_transform1<<<(NN + 127) / 128, 128>>>(x, W1);

    // layer-1 SpMM: 4 threads per edge
    k_spmm1<<<(int)(((long long)E_RSR * 4 + 255) / 256), 256>>>(0, 0, E_RSR);
    k_spmm1<<<(int)(((long long)E_RTR * 4 + 255) / 256), 256>>>(1, E_RSR, E_RTR);
    k_spmm1<<<(int)(((long long)E_RUR * 4 + 255) / 256), 256>>>(2, E_RSR + E_RTR, E_RUR);

    k_relu_g<<<(NN + 127) / 128, 128>>>(b1, W2);

    k_spmm2<<<(E_RSR + 255) / 256, 256>>>(0, 0, E_RSR, out);
    k_spmm2<<<(E_RTR + 255) / 256, 256>>>(1, E_RSR, E_RTR, out);
    k_spmm2<<<(E_RUR + 255) / 256, 256>>>(2, E_RSR + E_RTR, E_RUR, out);
}